// round 3
// baseline (speedup 1.0000x reference)
#include <cuda_runtime.h>

// RecursiveFilter: y[0]=x[0]; y[n] = W*x[n] + (1-W)*y[n-1] along axis 2 (N)
// Shape: [B=4, C=3, N=32, H=256, W=256] fp32, contiguous.
// One thread per float4 lane of (h,w). Recurrence serial only along N=32.
//
// R3 changes vs R2:
//  - 64-thread CTAs (3072 total) -> per-SM CTA-count imbalance 1.2% instead of 16%
//  - __ldcs/__stcs streaming hints (no reuse; keep the 201MB stream out of L2 policy)
//  - loads batched 4 frames ahead of the fma+store group (MLP_p1 = 4)

#define FW 0.3f
#define FW1 0.7f

static constexpr int Ndim = 32;
static constexpr int HW   = 256 * 256;   // elements per frame per (b,c)
static constexpr int HW4  = HW / 4;      // 16384 float4 per frame
static constexpr int BC   = 4 * 3;
static constexpr int TPB  = 64;

__device__ __forceinline__ float4 ema4(float4 v, float4 c) {
    float4 r;
    r.x = FW * v.x + FW1 * c.x;
    r.y = FW * v.y + FW1 * c.y;
    r.z = FW * v.z + FW1 * c.z;
    r.w = FW * v.w + FW1 * c.w;
    return r;
}

__global__ __launch_bounds__(TPB)
void recursive_filter_kernel(const float4* __restrict__ x,
                             float4* __restrict__ y)
{
    int hw4 = blockIdx.x * TPB + threadIdx.x;   // 0..HW4-1 (exact)
    int bc  = blockIdx.y;                       // 0..BC-1

    const float4* xp = x + (long)bc * Ndim * HW4 + hw4;
    float4*       yp = y + (long)bc * Ndim * HW4 + hw4;

    float4 c;

    // chunk 0: frames 0..3 (frame 0 is identity)
    {
        float4 v0 = __ldcs(xp + 0 * HW4);
        float4 v1 = __ldcs(xp + 1 * HW4);
        float4 v2 = __ldcs(xp + 2 * HW4);
        float4 v3 = __ldcs(xp + 3 * HW4);
        c = v0;            __stcs(yp + 0 * HW4, c);
        c = ema4(v1, c);   __stcs(yp + 1 * HW4, c);
        c = ema4(v2, c);   __stcs(yp + 2 * HW4, c);
        c = ema4(v3, c);   __stcs(yp + 3 * HW4, c);
    }

    // chunks 1..7: frames 4..31
#pragma unroll
    for (int n0 = 4; n0 < Ndim; n0 += 4) {
        float4 v0 = __ldcs(xp + (n0 + 0) * HW4);
        float4 v1 = __ldcs(xp + (n0 + 1) * HW4);
        float4 v2 = __ldcs(xp + (n0 + 2) * HW4);
        float4 v3 = __ldcs(xp + (n0 + 3) * HW4);
        c = ema4(v0, c);   __stcs(yp + (n0 + 0) * HW4, c);
        c = ema4(v1, c);   __stcs(yp + (n0 + 1) * HW4, c);
        c = ema4(v2, c);   __stcs(yp + (n0 + 2) * HW4, c);
        c = ema4(v3, c);   __stcs(yp + (n0 + 3) * HW4, c);
    }
}

extern "C" void kernel_launch(void* const* d_in, const int* in_sizes, int n_in,
                              void* d_out, int out_size)
{
    const float4* x = (const float4*)d_in[0];
    float4* y = (float4*)d_out;

    dim3 grid(HW4 / TPB, BC, 1);   // (256, 12) = 3072 CTAs of 64 threads
    recursive_filter_kernel<<<grid, TPB>>>(x, y);
}